// round 4
// baseline (speedup 1.0000x reference)
#include <cuda_runtime.h>
#include <cstdint>

#define E_    12
#define D_    768
#define KDIM  1536
#define NE    24
#define ROWS  32            // batch rows per tile (kernel 1)
#define KC    128           // K chunk
#define NCH   (KDIM / KC)   // 12
#define GSTR  132           // G row stride (floats): 528 B == 16 mod 128 -> conflict-free
#define WSTR  1540          // W row stride (floats): == 4 mod 32 -> conflict-free
#define BMAX  16384
#define R2    8             // rows per CTA (kernel 2)
#define NSM   148

#define GBUF  (ROWS * GSTR)                 // 4224 floats per G buffer
#define SMEM_FLOATS (NE * WSTR + 2 * GBUF + ROWS * NE)
#define SMEM_BYTES  (SMEM_FLOATS * 4)       // 184,704 B

// Cross-kernel handoff (static device arrays — allocation-free)
__device__ float g_scl[2 * BMAX];
__device__ int   g_idx[2 * BMAX];

__device__ __forceinline__ void ffma2(unsigned long long &d,
                                      unsigned long long a,
                                      unsigned long long b) {
    asm("fma.rn.f32x2 %0, %1, %2, %0;" : "+l"(d) : "l"(a), "l"(b));
}

__device__ __forceinline__ float2 unpack2(unsigned long long v) {
    float2 r;
    asm("mov.b64 {%0, %1}, %2;" : "=f"(r.x), "=f"(r.y) : "l"(v));
    return r;
}

// ── Kernel 1: persistent, W-resident, double-buffered logits + gumbel-softmax-ST ──
__global__ void __launch_bounds__(256) gate_logits_kernel(
    const float* __restrict__ audio, const float* __restrict__ image,
    const float* __restrict__ Wa,    const float* __restrict__ ba,
    const float* __restrict__ Wi,    const float* __restrict__ bi,
    const float* __restrict__ ga,    const float* __restrict__ gi,
    float* __restrict__ out, int B, int ntiles)
{
    extern __shared__ float sm[];
    float* Wsm = sm;                       // NE x WSTR (resident)
    float* Gsm = sm + NE * WSTR;           // 2 x ROWS x GSTR (double buffer)
    float* Lp  = Gsm;                      // alias: 8 x ROWS x NE split-K partials
    float* Ls  = Gsm + 2 * GBUF;           // ROWS x NE reduced logits

    const int tid = threadIdx.x;
    const int ks  = tid >> 5;              // warp = K-slice within chunk (16 floats)
    const int rg  = (tid >> 2) & 7;        // rows rg, rg+8, rg+16, rg+24
    const int eg  = tid & 3;               // experts eg, eg+4, ..., eg+20
    const int sr  = tid >> 3;              // staging row (0..31)
    const int q0  = tid & 7;               // staging quad base

    const size_t rowstride = (size_t)E_ * D_;  // 9216

    // Stage full W once: 24 x 384 quads, 36/thread
    for (int i = tid; i < NE * (KDIM / 4); i += 256) {
        int e = i / (KDIM / 4);
        int q = i - e * (KDIM / 4);
        const float* wsrc = (e < E_) ? (Wa + (size_t)e * KDIM)
                                     : (Wi + (size_t)(e - E_) * KDIM);
        *(float4*)(Wsm + e * WSTR + q * 4) = *(const float4*)(wsrc + q * 4);
    }
    __syncthreads();

    for (int tile = blockIdx.x; tile < ntiles; tile += gridDim.x) {
        const int row0 = tile * ROWS;
        int b = row0 + sr; if (b >= B) b = B - 1;
        const float* arow = audio + (size_t)b * rowstride;
        const float* irow = image + (size_t)b * rowstride;

        // Stage chunk 0 into buffer 0
        #pragma unroll
        for (int j = 0; j < 4; j++) {
            int q = q0 + 8 * j;
            *(float4*)(Gsm + sr * GSTR + q * 4) = *(const float4*)(arow + q * 4);
        }
        __syncthreads();

        unsigned long long acc[6][4];
        #pragma unroll
        for (int m = 0; m < 6; m++)
            #pragma unroll
            for (int i = 0; i < 4; i++) acc[m][i] = 0ULL;

        for (int c = 0; c < NCH; c++) {
            // Prefetch chunk c+1 into registers (overlaps with compute below)
            float4 pv[4];
            if (c < NCH - 1) {
                const int cn = c + 1;
                const float* rp = (cn < NCH / 2) ? (arow + cn * KC)
                                                 : (irow + cn * KC - D_);
                #pragma unroll
                for (int j = 0; j < 4; j++)
                    pv[j] = *(const float4*)(rp + (q0 + 8 * j) * 4);
            }

            // Compute chunk c from buffer c&1
            const float* gb = Gsm + (c & 1) * GBUF;
            const int cb = ks * 16;
            #pragma unroll
            for (int kk = 0; kk < 4; kk++) {
                const int col = cb + kk * 4;
                ulonglong2 g0 = *(const ulonglong2*)(gb + (rg     ) * GSTR + col);
                ulonglong2 g1 = *(const ulonglong2*)(gb + (rg +  8) * GSTR + col);
                ulonglong2 g2 = *(const ulonglong2*)(gb + (rg + 16) * GSTR + col);
                ulonglong2 g3 = *(const ulonglong2*)(gb + (rg + 24) * GSTR + col);
                #pragma unroll
                for (int m = 0; m < 6; m++) {
                    ulonglong2 w = *(const ulonglong2*)(Wsm + (eg + 4 * m) * WSTR
                                                        + c * KC + col);
                    ffma2(acc[m][0], g0.x, w.x); ffma2(acc[m][0], g0.y, w.y);
                    ffma2(acc[m][1], g1.x, w.x); ffma2(acc[m][1], g1.y, w.y);
                    ffma2(acc[m][2], g2.x, w.x); ffma2(acc[m][2], g2.y, w.y);
                    ffma2(acc[m][3], g3.x, w.x); ffma2(acc[m][3], g3.y, w.y);
                }
            }

            if (c < NCH - 1) {
                float* dst = Gsm + ((c + 1) & 1) * GBUF + sr * GSTR;
                #pragma unroll
                for (int j = 0; j < 4; j++)
                    *(float4*)(dst + (q0 + 8 * j) * 4) = pv[j];
            }
            __syncthreads();
        }

        // Deposit split-K partials (aliases G buffers; all reads done at last sync)
        #pragma unroll
        for (int m = 0; m < 6; m++)
            #pragma unroll
            for (int i = 0; i < 4; i++) {
                float2 p = unpack2(acc[m][i]);
                Lp[ks * (ROWS * NE) + (rg + 8 * i) * NE + (eg + 4 * m)] = p.x + p.y;
            }
        __syncthreads();

        // Reduce over 8 K-slices in fixed order: 768 entries, 3/thread
        #pragma unroll
        for (int t = 0; t < 3; t++) {
            int idx = tid * 3 + t;
            int r = idx / NE;
            int e = idx - r * NE;
            float s = 0.f;
            #pragma unroll
            for (int k = 0; k < 8; k++) s += Lp[k * (ROWS * NE) + r * NE + e];
            Ls[r * NE + e] = s;
        }
        __syncthreads();

        // Gumbel-softmax straight-through per row (one thread per row)
        if (tid < ROWS) {
            int bb = row0 + tid;
            if (bb < B) {
                float* retA = out + (size_t)B * KDIM;
                float* retI = retA + (size_t)B * E_;
                #pragma unroll
                for (int gsel = 0; gsel < 2; gsel++) {
                    const float* bias = gsel ? bi : ba;
                    const float* gum  = gsel ? gi : ga;
                    float* retp       = gsel ? retI : retA;
                    float l[E_];
                    float mx = -1e30f;
                    #pragma unroll
                    for (int e = 0; e < E_; e++) {
                        l[e] = Ls[tid * NE + gsel * E_ + e] + bias[e]
                             + gum[(size_t)bb * E_ + e];
                        mx = fmaxf(mx, l[e]);
                    }
                    float s = 0.f;
                    float y[E_];
                    #pragma unroll
                    for (int e = 0; e < E_; e++) { y[e] = expf(l[e] - mx); s += y[e]; }
                    const float inv = 1.0f / s;
                    float ys[E_];
                    int   am = 0;
                    float best = y[0] * inv;
                    ys[0] = best;
                    #pragma unroll
                    for (int e = 1; e < E_; e++) {
                        ys[e] = y[e] * inv;
                        if (ys[e] > best) { best = ys[e]; am = e; }  // first-max
                    }
                    #pragma unroll
                    for (int e = 0; e < E_; e++) {
                        float h = (e == am) ? 1.0f : 0.0f;
                        retp[(size_t)bb * E_ + e] = (h - ys[e]) + ys[e];  // exact ref
                    }
                    g_scl[gsel * BMAX + bb] = ((1.0f - ys[am]) + ys[am]) * (1.0f / 12.0f);
                    g_idx[gsel * BMAX + bb] = am;
                }
            }
        }
        // Next tile's staging (writes Lp-aliased region) is safe: reduce readers
        // synced above; softmax touches only Ls/gmem and joins at the next barrier.
    }
}

// ───────────── Kernel 2: gather selected expert rows, scale, store ─────────────
__global__ void __launch_bounds__(256) gate_gather_kernel(
    const float* __restrict__ audio, const float* __restrict__ image,
    float* __restrict__ out, int B)
{
    __shared__ float s_scl[2][R2];
    __shared__ int   s_idx[2][R2];

    const int tid  = threadIdx.x;
    const int row0 = blockIdx.x * R2;

    if (tid < 2 * R2) {
        int gsel = tid >> 3;       // R2 == 8
        int r    = tid & 7;
        int b    = row0 + r;
        if (b < B) {
            s_scl[gsel][r] = g_scl[gsel * BMAX + b];
            s_idx[gsel][r] = g_idx[gsel * BMAX + b];
        }
    }
    __syncthreads();

    const int V4 = KDIM / 4;  // 384 float4 per row
    #pragma unroll
    for (int j = 0; j < (R2 * V4) / 256; j++) {   // 12 iterations
        int i = tid + j * 256;
        int r = i / V4;
        int c = i - r * V4;
        int b = row0 + r;
        if (b >= B) continue;
        float4 v;
        float  s;
        if (c < (D_ / 4)) {
            v = *(const float4*)(audio + ((size_t)b * E_ + s_idx[0][r]) * D_ + c * 4);
            s = s_scl[0][r];
        } else {
            v = *(const float4*)(image + ((size_t)b * E_ + s_idx[1][r]) * D_ + (c - D_ / 4) * 4);
            s = s_scl[1][r];
        }
        v.x *= s; v.y *= s; v.z *= s; v.w *= s;
        *(float4*)(out + (size_t)b * KDIM + c * 4) = v;
    }
}

extern "C" void kernel_launch(void* const* d_in, const int* in_sizes, int n_in,
                              void* d_out, int out_size) {
    const float* audio = (const float*)d_in[0];
    const float* image = (const float*)d_in[1];
    const float* Wa    = (const float*)d_in[2];
    const float* ba    = (const float*)d_in[3];
    const float* Wi    = (const float*)d_in[4];
    const float* bi    = (const float*)d_in[5];
    const float* ga    = (const float*)d_in[6];
    const float* gi    = (const float*)d_in[7];
    float* out = (float*)d_out;

    const int B = in_sizes[0] / (E_ * D_);     // 16384
    const int ntiles = (B + ROWS - 1) / ROWS;  // 512

    static bool attr_set = false;
    if (!attr_set) {
        cudaFuncSetAttribute(gate_logits_kernel,
                             cudaFuncAttributeMaxDynamicSharedMemorySize, SMEM_BYTES);
        attr_set = true;
    }

    gate_logits_kernel<<<NSM, 256, SMEM_BYTES>>>(audio, image, Wa, ba, Wi, bi,
                                                 ga, gi, out, B, ntiles);

    const int grid2 = (B + R2 - 1) / R2;       // 2048
    gate_gather_kernel<<<grid2, 256>>>(audio, image, out, B);
}

// round 5
// speedup vs baseline: 1.1180x; 1.1180x over previous
#include <cuda_runtime.h>
#include <cstdint>

#define E_    12
#define D_    768
#define KDIM  1536
#define NE    24
#define ROWS  32            // batch rows per CTA tile
#define KC    128           // K chunk
#define NCH   12            // KDIM / KC
#define GSTR  132           // G row stride (floats), 528B == 16 mod 128 -> conflict-free
#define WSTR  132           // W chunk row stride
#define GBUF  (ROWS * GSTR) // 4224 floats per buffer
#define WBUF  (NE * WSTR)   // 3168 floats per buffer

__device__ __forceinline__ void ffma2(unsigned long long &d,
                                      unsigned long long a,
                                      unsigned long long b) {
    asm("fma.rn.f32x2 %0, %1, %2, %0;" : "+l"(d) : "l"(a), "l"(b));
}
__device__ __forceinline__ float2 unpack2(unsigned long long v) {
    float2 r;
    asm("mov.b64 {%0, %1}, %2;" : "=f"(r.x), "=f"(r.y) : "l"(v));
    return r;
}
__device__ __forceinline__ void cp16(uint32_t dst, const float* src) {
    asm volatile("cp.async.cg.shared.global [%0], [%1], 16;" :: "r"(dst), "l"(src));
}

// ── Fused: cp.async-pipelined logits GEMM + gumbel-softmax-ST + gather ──
__global__ void __launch_bounds__(256, 2) gate_fused(
    const float* __restrict__ audio, const float* __restrict__ image,
    const float* __restrict__ Wa,    const float* __restrict__ ba,
    const float* __restrict__ Wi,    const float* __restrict__ bi,
    const float* __restrict__ ga,    const float* __restrict__ gi,
    float* __restrict__ out, int B)
{
    extern __shared__ float sm[];
    float* Gm    = sm;                     // 2 x GBUF (double buffer)
    float* Wm    = sm + 2 * GBUF;          // 2 x WBUF (double buffer)
    float* Ls    = Wm + 2 * WBUF;          // ROWS x NE reduced logits
    float* s_scl = Ls + ROWS * NE;         // 2 x ROWS
    int*   s_idx = (int*)(s_scl + 2 * ROWS);
    float* Lp    = Gm;                     // alias: 8 x ROWS x NE split-K partials

    const int tid  = threadIdx.x;
    const int ks   = tid >> 5;             // warp = K-slice (16 floats per chunk)
    const int lane = tid & 31;
    const int rp   = lane >> 1;            // rows rp, rp+16
    const int eh   = (lane & 1) * 12;      // expert half: 0..11 or 12..23
    const int row0 = blockIdx.x * ROWS;

    const uint32_t gsm = (uint32_t)__cvta_generic_to_shared(Gm);
    const uint32_t wsm = (uint32_t)__cvta_generic_to_shared(Wm);
    const size_t rowstride = (size_t)E_ * D_;   // 9216

    unsigned long long acc[12][2];
    #pragma unroll
    for (int m = 0; m < 12; m++) { acc[m][0] = 0ULL; acc[m][1] = 0ULL; }

    // ---- staging: one K-chunk of G (32x128) and W (24x128) via cp.async ----
    auto stage = [&](int c) {
        const int buf = c & 1;
        const float* src = (c < NCH / 2) ? audio : image;
        const int kb = (c < NCH / 2) ? c * KC : c * KC - D_;
        #pragma unroll
        for (int j = 0; j < 4; j++) {          // G: 1024 quads, 4/thread
            int i = tid + j * 256;
            int r = i >> 5, q = i & 31;
            int b = row0 + r; if (b >= B) b = B - 1;
            cp16(gsm + (uint32_t)((buf * GBUF + r * GSTR + q * 4) * 4),
                 src + (size_t)b * rowstride + kb + q * 4);
        }
        #pragma unroll
        for (int j = 0; j < 3; j++) {          // W: 768 quads, 3/thread
            int i = tid + j * 256;
            int e = i >> 5, q = i & 31;
            const float* ws = (e < E_) ? Wa + (size_t)e * KDIM
                                       : Wi + (size_t)(e - E_) * KDIM;
            cp16(wsm + (uint32_t)((buf * WBUF + e * WSTR + q * 4) * 4),
                 ws + c * KC + q * 4);
        }
        asm volatile("cp.async.commit_group;");
    };

    stage(0);

    for (int c = 0; c < NCH; c++) {
        if (c + 1 < NCH) {
            stage(c + 1);
            asm volatile("cp.async.wait_group 1;");
        } else {
            asm volatile("cp.async.wait_group 0;");
        }
        __syncthreads();

        const float* gb = Gm + (c & 1) * GBUF;
        const float* wb = Wm + (c & 1) * WBUF;
        const int cb = ks * 16;
        #pragma unroll
        for (int kk = 0; kk < 4; kk++) {
            const int col = cb + kk * 4;
            ulonglong2 g0 = *(const ulonglong2*)(gb + rp * GSTR + col);
            ulonglong2 g1 = *(const ulonglong2*)(gb + (rp + 16) * GSTR + col);
            #pragma unroll
            for (int m = 0; m < 12; m++) {
                ulonglong2 w = *(const ulonglong2*)(wb + (eh + m) * WSTR + col);
                ffma2(acc[m][0], g0.x, w.x); ffma2(acc[m][0], g0.y, w.y);
                ffma2(acc[m][1], g1.x, w.x); ffma2(acc[m][1], g1.y, w.y);
            }
        }
        __syncthreads();   // compute done before next stage overwrites / Lp alias
    }

    // ---- deposit split-K partials (deterministic order) ----
    #pragma unroll
    for (int m = 0; m < 12; m++) {
        float2 p0 = unpack2(acc[m][0]);
        float2 p1 = unpack2(acc[m][1]);
        Lp[(ks * ROWS + rp) * NE + eh + m]        = p0.x + p0.y;
        Lp[(ks * ROWS + rp + 16) * NE + eh + m]   = p1.x + p1.y;
    }
    __syncthreads();

    // ---- reduce 8 K-slices in fixed order: 768 sums, 3/thread ----
    #pragma unroll
    for (int t = 0; t < 3; t++) {
        int idx = tid * 3 + t;
        int r = idx / NE;
        int e = idx - r * NE;
        float s = 0.f;
        #pragma unroll
        for (int k = 0; k < 8; k++) s += Lp[(k * ROWS + r) * NE + e];
        Ls[r * NE + e] = s;
    }
    __syncthreads();

    // ---- gumbel-softmax straight-through (one thread per row) ----
    if (tid < ROWS) {
        int b = row0 + tid;
        if (b < B) {
            float* retA = out + (size_t)B * KDIM;
            float* retI = retA + (size_t)B * E_;
            #pragma unroll
            for (int gsel = 0; gsel < 2; gsel++) {
                const float* bias = gsel ? bi : ba;
                const float* gum  = gsel ? gi : ga;
                float* retp       = gsel ? retI : retA;
                float l[E_];
                float mx = -1e30f;
                #pragma unroll
                for (int e = 0; e < E_; e++) {
                    l[e] = Ls[tid * NE + gsel * E_ + e] + bias[e]
                         + gum[(size_t)b * E_ + e];
                    mx = fmaxf(mx, l[e]);
                }
                float s = 0.f;
                float y[E_];
                #pragma unroll
                for (int e = 0; e < E_; e++) { y[e] = expf(l[e] - mx); s += y[e]; }
                const float inv = 1.0f / s;
                float ys[E_];
                int   am = 0;
                float best = y[0] * inv;
                ys[0] = best;
                #pragma unroll
                for (int e = 1; e < E_; e++) {
                    ys[e] = y[e] * inv;
                    if (ys[e] > best) { best = ys[e]; am = e; }  // first-max (jnp.argmax)
                }
                #pragma unroll
                for (int e = 0; e < E_; e++) {
                    float h = (e == am) ? 1.0f : 0.0f;
                    retp[(size_t)b * E_ + e] = (h - ys[e]) + ys[e];  // exact ref arithmetic
                }
                s_scl[gsel * ROWS + tid] = ((1.0f - ys[am]) + ys[am]) * (1.0f / 12.0f);
                s_idx[gsel * ROWS + tid] = am;
            }
        }
    }
    __syncthreads();

    // ---- gather selected expert rows, scale, store: 32 x 384 quads ----
    const int V4 = KDIM / 4;  // 384
    #pragma unroll 4
    for (int j = 0; j < (ROWS * V4) / 256; j++) {   // 48 iterations
        int i = tid + j * 256;
        int r = i / V4;
        int c2 = i - r * V4;
        int b = row0 + r;
        if (b >= B) continue;
        float4 v;
        float  s;
        if (c2 < (D_ / 4)) {
            v = *(const float4*)(audio + ((size_t)b * E_ + s_idx[r]) * D_ + c2 * 4);
            s = s_scl[r];
        } else {
            v = *(const float4*)(image + ((size_t)b * E_ + s_idx[ROWS + r]) * D_
                                 + (c2 - D_ / 4) * 4);
            s = s_scl[ROWS + r];
        }
        v.x *= s; v.y *= s; v.z *= s; v.w *= s;
        *(float4*)(out + (size_t)b * KDIM + c2 * 4) = v;
    }
}

#define SMEM_BYTES ((2 * GBUF + 2 * WBUF + ROWS * NE + 2 * ROWS) * 4 + 2 * ROWS * 4)

extern "C" void kernel_launch(void* const* d_in, const int* in_sizes, int n_in,
                              void* d_out, int out_size) {
    const float* audio = (const float*)d_in[0];
    const float* image = (const float*)d_in[1];
    const float* Wa    = (const float*)d_in[2];
    const float* ba    = (const float*)d_in[3];
    const float* Wi    = (const float*)d_in[4];
    const float* bi    = (const float*)d_in[5];
    const float* ga    = (const float*)d_in[6];
    const float* gi    = (const float*)d_in[7];
    float* out = (float*)d_out;

    const int B = in_sizes[0] / (E_ * D_);     // 16384
    const int grid = (B + ROWS - 1) / ROWS;    // 512

    static bool attr_set = false;
    if (!attr_set) {
        cudaFuncSetAttribute(gate_fused,
                             cudaFuncAttributeMaxDynamicSharedMemorySize, SMEM_BYTES);
        attr_set = true;
    }

    gate_fused<<<grid, 256, SMEM_BYTES>>>(audio, image, Wa, ba, Wi, bi,
                                          ga, gi, out, B);
}

// round 6
// speedup vs baseline: 1.3728x; 1.2280x over previous
#include <cuda_runtime.h>
#include <cstdint>

#define E_    12
#define D_    768
#define KDIM  1536
#define NE    24
#define ROWS  32            // batch rows per CTA tile (K1)
#define KC    128           // K chunk
#define NCH   12            // KDIM / KC
#define GSTR  132           // G row stride (floats): 528B == 16 mod 128 -> conflict-free
#define WSTR  132           // W chunk row stride
#define GBUF  (ROWS * GSTR) // 4224 floats
#define WBUF  (NE * WSTR)   // 3168 floats
#define BMAX  16384

// Cross-kernel handoff (static device arrays — allocation-free)
__device__ float g_scl[2 * BMAX];
__device__ int   g_idx[2 * BMAX];

__device__ __forceinline__ void ffma2(unsigned long long &d,
                                      unsigned long long a,
                                      unsigned long long b) {
    asm("fma.rn.f32x2 %0, %1, %2, %0;" : "+l"(d) : "l"(a), "l"(b));
}
__device__ __forceinline__ float2 unpack2(unsigned long long v) {
    float2 r;
    asm("mov.b64 {%0, %1}, %2;" : "=f"(r.x), "=f"(r.y) : "l"(v));
    return r;
}
__device__ __forceinline__ void cp16(uint32_t dst, const float* src) {
    asm volatile("cp.async.cg.shared.global [%0], [%1], 16;" :: "r"(dst), "l"(src));
}

// ── Kernel 1: cp.async-pipelined logits GEMM + gumbel-softmax-ST + ret writes ──
__global__ void __launch_bounds__(256, 3) gate_logits(
    const float* __restrict__ audio, const float* __restrict__ image,
    const float* __restrict__ Wa,    const float* __restrict__ ba,
    const float* __restrict__ Wi,    const float* __restrict__ bi,
    const float* __restrict__ ga,    const float* __restrict__ gi,
    float* __restrict__ out, int B)
{
    extern __shared__ float sm[];
    float* Gm = sm;                    // 2 x GBUF (double buffer)
    float* Wm = sm + 2 * GBUF;         // 2 x WBUF (double buffer)
    float* Ls = Wm + 2 * WBUF;         // ROWS x NE reduced logits
    float* Lp = Gm;                    // alias: 4 x ROWS x NE split-K partials (3072 f)

    const int tid  = threadIdx.x;
    const int lane = tid & 31;
    const int wid  = tid >> 5;
    const int ksl  = wid & 3;          // K-slice: floats ksl*32 .. +31 of each chunk
    const int rh   = wid >> 2;         // row half (0..1)
    const int rp   = lane >> 2;        // row pair base (0..7)
    const int eg   = lane & 3;         // expert group: experts eg*6 .. eg*6+5
    const int r0   = rh * 16 + rp;     // rows r0, r0+8
    const int row0 = blockIdx.x * ROWS;

    const uint32_t gsm = (uint32_t)__cvta_generic_to_shared(Gm);
    const uint32_t wsm = (uint32_t)__cvta_generic_to_shared(Wm);
    const size_t rowstride = (size_t)E_ * D_;   // 9216

    unsigned long long acc[6][2];
    #pragma unroll
    for (int m = 0; m < 6; m++) { acc[m][0] = 0ULL; acc[m][1] = 0ULL; }

    auto stage = [&](int c) {
        const int buf = c & 1;
        const float* src = (c < NCH / 2) ? audio : image;
        const int kb = (c < NCH / 2) ? c * KC : c * KC - D_;
        #pragma unroll
        for (int j = 0; j < 4; j++) {            // G: 1024 quads, 4/thread
            int i = tid + j * 256;
            int r = i >> 5, q = i & 31;
            int b = row0 + r; if (b >= B) b = B - 1;
            cp16(gsm + (uint32_t)((buf * GBUF + r * GSTR + q * 4) * 4),
                 src + (size_t)b * rowstride + kb + q * 4);
        }
        #pragma unroll
        for (int j = 0; j < 3; j++) {            // W: 768 quads, 3/thread
            int i = tid + j * 256;
            int e = i >> 5, q = i & 31;
            const float* ws = (e < E_) ? Wa + (size_t)e * KDIM
                                       : Wi + (size_t)(e - E_) * KDIM;
            cp16(wsm + (uint32_t)((buf * WBUF + e * WSTR + q * 4) * 4),
                 ws + c * KC + q * 4);
        }
        asm volatile("cp.async.commit_group;");
    };

    stage(0);

    for (int c = 0; c < NCH; c++) {
        if (c + 1 < NCH) {
            stage(c + 1);
            asm volatile("cp.async.wait_group 1;");
        } else {
            asm volatile("cp.async.wait_group 0;");
        }
        __syncthreads();

        const float* gb = Gm + (c & 1) * GBUF;
        const float* wb = Wm + (c & 1) * WBUF;
        const int cb = ksl * 32;
        #pragma unroll
        for (int kk = 0; kk < 8; kk++) {
            const int col = cb + kk * 4;
            ulonglong2 g0 = *(const ulonglong2*)(gb + r0 * GSTR + col);
            ulonglong2 g1 = *(const ulonglong2*)(gb + (r0 + 8) * GSTR + col);
            #pragma unroll
            for (int m = 0; m < 6; m++) {
                ulonglong2 w = *(const ulonglong2*)(wb + (eg * 6 + m) * WSTR + col);
                ffma2(acc[m][0], g0.x, w.x); ffma2(acc[m][0], g0.y, w.y);
                ffma2(acc[m][1], g1.x, w.x); ffma2(acc[m][1], g1.y, w.y);
            }
        }
        __syncthreads();   // all reads done before restage / Lp alias
    }

    // Deposit split-K partials (deterministic order)
    #pragma unroll
    for (int m = 0; m < 6; m++) {
        float2 p0 = unpack2(acc[m][0]);
        float2 p1 = unpack2(acc[m][1]);
        Lp[(ksl * ROWS + r0) * NE + eg * 6 + m]       = p0.x + p0.y;
        Lp[(ksl * ROWS + r0 + 8) * NE + eg * 6 + m]   = p1.x + p1.y;
    }
    __syncthreads();

    // Reduce 4 K-slices in fixed order: 768 sums, 3/thread
    #pragma unroll
    for (int t = 0; t < 3; t++) {
        int idx = tid * 3 + t;
        int r = idx / NE;
        int e = idx - r * NE;
        float s = 0.f;
        #pragma unroll
        for (int k = 0; k < 4; k++) s += Lp[(k * ROWS + r) * NE + e];
        Ls[r * NE + e] = s;
    }
    __syncthreads();

    // Gumbel-softmax straight-through (one thread per row)
    if (tid < ROWS) {
        int b = row0 + tid;
        if (b < B) {
            float* retA = out + (size_t)B * KDIM;
            float* retI = retA + (size_t)B * E_;
            #pragma unroll
            for (int gsel = 0; gsel < 2; gsel++) {
                const float* bias = gsel ? bi : ba;
                const float* gum  = gsel ? gi : ga;
                float* retp       = gsel ? retI : retA;
                float l[E_];
                float mx = -1e30f;
                #pragma unroll
                for (int e = 0; e < E_; e++) {
                    l[e] = Ls[tid * NE + gsel * E_ + e] + bias[e]
                         + gum[(size_t)b * E_ + e];
                    mx = fmaxf(mx, l[e]);
                }
                float s = 0.f;
                float y[E_];
                #pragma unroll
                for (int e = 0; e < E_; e++) { y[e] = expf(l[e] - mx); s += y[e]; }
                const float inv = 1.0f / s;
                float ys[E_];
                int   am = 0;
                float best = y[0] * inv;
                ys[0] = best;
                #pragma unroll
                for (int e = 1; e < E_; e++) {
                    ys[e] = y[e] * inv;
                    if (ys[e] > best) { best = ys[e]; am = e; }  // first-max (jnp.argmax)
                }
                #pragma unroll
                for (int e = 0; e < E_; e++) {
                    float h = (e == am) ? 1.0f : 0.0f;
                    retp[(size_t)b * E_ + e] = (h - ys[e]) + ys[e];  // exact ref arithmetic
                }
                g_scl[gsel * BMAX + b] = ((1.0f - ys[am]) + ys[am]) * (1.0f / 12.0f);
                g_idx[gsel * BMAX + b] = am;
            }
        }
    }
}

// ── Kernel 2: gather — warp per row, 12 independent LDG.128 per lane ──
__global__ void __launch_bounds__(256) gate_gather(
    const float* __restrict__ audio, const float* __restrict__ image,
    float* __restrict__ out, int B)
{
    const int wid  = threadIdx.x >> 5;
    const int lane = threadIdx.x & 31;
    const int b    = blockIdx.x * 8 + wid;
    if (b >= B) return;

    const float sa = g_scl[b]          ;
    const float si = g_scl[BMAX + b];
    const int   ia = g_idx[b];
    const int   ii = g_idx[BMAX + b];

    const float* ap = audio + ((size_t)b * E_ + ia) * D_;
    const float* ip = image + ((size_t)b * E_ + ii) * D_;
    float*       op = out + (size_t)b * KDIM;

    float4 v[12];
    #pragma unroll
    for (int j = 0; j < 6; j++)
        v[j] = *(const float4*)(ap + (lane + 32 * j) * 4);
    #pragma unroll
    for (int j = 0; j < 6; j++)
        v[6 + j] = *(const float4*)(ip + (lane + 32 * j) * 4);

    #pragma unroll
    for (int j = 0; j < 6; j++) {
        float4 t = v[j];
        t.x *= sa; t.y *= sa; t.z *= sa; t.w *= sa;
        *(float4*)(op + (lane + 32 * j) * 4) = t;
    }
    #pragma unroll
    for (int j = 0; j < 6; j++) {
        float4 t = v[6 + j];
        t.x *= si; t.y *= si; t.z *= si; t.w *= si;
        *(float4*)(op + D_ + (lane + 32 * j) * 4) = t;
    }
}

#define SMEM_BYTES ((2 * GBUF + 2 * WBUF + ROWS * NE) * 4)

extern "C" void kernel_launch(void* const* d_in, const int* in_sizes, int n_in,
                              void* d_out, int out_size) {
    const float* audio = (const float*)d_in[0];
    const float* image = (const float*)d_in[1];
    const float* Wa    = (const float*)d_in[2];
    const float* ba    = (const float*)d_in[3];
    const float* Wi    = (const float*)d_in[4];
    const float* bi    = (const float*)d_in[5];
    const float* ga    = (const float*)d_in[6];
    const float* gi    = (const float*)d_in[7];
    float* out = (float*)d_out;

    const int B = in_sizes[0] / (E_ * D_);     // 16384

    static bool attr_set = false;
    if (!attr_set) {
        cudaFuncSetAttribute(gate_logits,
                             cudaFuncAttributeMaxDynamicSharedMemorySize, SMEM_BYTES);
        attr_set = true;
    }

    const int grid1 = (B + ROWS - 1) / ROWS;   // 512
    gate_logits<<<grid1, 256, SMEM_BYTES>>>(audio, image, Wa, ba, Wi, bi,
                                            ga, gi, out, B);

    const int grid2 = (B + 7) / 8;             // 2048
    gate_gather<<<grid2, 256>>>(audio, image, out, B);
}